// round 17
// baseline (speedup 1.0000x reference)
#include <cuda_runtime.h>
#include <cuda_bf16.h>

// ---------------- problem constants ----------------
#define BATCH   4
#define NPTS    32768
#define NCLS    3
#define KSEL    4096          // NMS_PRE_MAXSIZE
#define KPOST   512           // NMS_POST_MAXSIZE
#define NWORDS  64            // 4096 / 64
#define NW1     16            // stage-0: first 1024 boxes
#define NBUCK   4096          // fine monotone buckets
#define CAND_CAP 6144         // smem candidate staging capacity
#define NCAP    320           // compacted-row smem capacity (scan tail)

#define ROIS_ELEMS   (BATCH * KPOST * 7)          // 14336
#define SC_OFF       (ROIS_ELEMS)                 // 14336
#define LB_OFF       (ROIS_ELEMS + BATCH * KPOST) // 16384
#define OUT_TOTAL    (ROIS_ELEMS + 2 * BATCH * KPOST) // 18432

// ---------------- device scratch (no allocations allowed) ----------------
__device__ int                g_hist[BATCH][NBUCK];         // self-zeroed by k_select
__device__ unsigned long long g_keyfull[BATCH][NPTS];       // 1 MB
__device__ unsigned long long g_cand[BATCH][NPTS];          // overflow path only
__device__ float4             g_box4[BATCH][KSEL];          // x1,y1,x2,y2
__device__ float              g_area[BATCH][KSEL];
__device__ float              g_rois[BATCH][KSEL][7];
__device__ float              g_scores[BATCH][KSEL];
__device__ unsigned char      g_labels[BATCH][KSEL];
__device__ unsigned long long g_mask0[BATCH][1024 * NW1];   // 512 KB [row][word16]
__device__ unsigned long long g_rownz[BATCH][NW1];          // zeroed by k_select
__device__ int                g_blkdone[BATCH];             // zeroed by tail block

// ---------------- helpers ----------------
__device__ __forceinline__ unsigned f2ord(float s) {
    unsigned u = __float_as_uint(s);
    return (u & 0x80000000u) ? ~u : (u | 0x80000000u);
}

// monotone (non-decreasing in u) bucket; fine resolution for s>=0.5
__device__ __forceinline__ int bucket_of(unsigned u) {
    if (u >= 0xBF000000u) {
        unsigned f = 2048u + ((u - 0xBF000000u) >> 12);
        return (int)(f > 4095u ? 4095u : f);
    }
    return (int)(u >> 21);                           // <= 1528 < 2048, monotone
}

__device__ __forceinline__ unsigned long long below_mask(int bit) {
    return (bit == 0) ? 0ull : (~0ull >> (64 - bit));
}

// exact-rounding IOU>thresh, identical op order to reference
__device__ __forceinline__ bool iou_gt(float4 A, float aA, float4 B, float aB) {
    float ix = __fsub_rn(fminf(A.z, B.z), fmaxf(A.x, B.x));
    float iy = __fsub_rn(fminf(A.w, B.w), fmaxf(A.y, B.y));
    if (ix > 0.0f && iy > 0.0f) {
        float inter = __fmul_rn(ix, iy);
        float denom = __fadd_rn(__fsub_rn(__fadd_rn(aA, aB), inter), 1e-6f);
        return __fdiv_rn(inter, denom) > 0.7f;
    }
    return false;
}

// ================= K1: keys + direct-RED histogram + output zeroing ==========
__global__ void __launch_bounds__(256)
k_keys_hist(const float* __restrict__ cls, float* __restrict__ out) {
    int gi = blockIdx.x * 256 + threadIdx.x;         // 0 .. 131071
    int b = gi >> 15, i = gi & (NPTS - 1);
    const float* cp = cls + (size_t)gi * NCLS;
    float s = fmaxf(fmaxf(cp[0], cp[1]), cp[2]);
    unsigned u = f2ord(s);
    g_keyfull[b][i] = ((unsigned long long)u << 32) |
                      (unsigned long long)(0xFFFFFFFFu - (unsigned)i);
    atomicAdd(&g_hist[b][bucket_of(u)], 1);          // result unused -> RED

    if (gi < OUT_TOTAL) out[gi] = 0.0f;              // zero poisoned output
}

// ================= K2: per-batch scan+scatter+rank+gather ====================
__global__ void __launch_bounds__(1024)
k_select(const float* __restrict__ boxes, const float* __restrict__ cls) {
    extern __shared__ unsigned char dsm[];
    int* s_cur  = (int*)dsm;                         // 4096 ints (scatter cursors)
    int* s_base = (int*)(dsm + 16384);               // 4096 ints
    unsigned long long* s_keys = (unsigned long long*)(dsm + 32768); // 6144 keys

    __shared__ int s_wsum[32];
    __shared__ int s_wsuf[33];
    __shared__ int s_max;

    int b = blockIdx.x, t = threadIdx.x;
    int lane = t & 31, wrp = t >> 5;
    const float* cb  = cls   + (size_t)b * NPTS * NCLS;
    const float* bx0 = boxes + (size_t)b * NPTS * 7;
    const unsigned long long* kf = g_keyfull[b];

    if (t == 0) s_max = 0;
    if (t < NW1) g_rownz[b][t] = 0ull;               // reset for mask0's atomicOr

    // ---- read histogram (coalesced), self-zero for next replay ----
    int h[4];
    int own = 0;
    const int b0 = t * 4;
#pragma unroll
    for (int k = 0; k < 4; k++) { h[k] = g_hist[b][b0 + k]; own += h[k]; }
#pragma unroll
    for (int k = 0; k < 4; k++) g_hist[b][b0 + k] = 0;

    // ---- suffix scan: warp shuffles + one cross-warp step ----
    int v = own;
#pragma unroll
    for (int d = 1; d < 32; d <<= 1) {
        int o = __shfl_down_sync(0xFFFFFFFFu, v, d);
        if (lane + d < 32) v += o;
    }
    if (lane == 0) s_wsum[wrp] = v;
    __syncthreads();
    if (wrp == 0) {
        int wv = s_wsum[lane];
#pragma unroll
        for (int d = 1; d < 32; d <<= 1) {
            int o = __shfl_down_sync(0xFFFFFFFFu, wv, d);
            if (lane + d < 32) wv += o;
        }
        s_wsuf[lane] = wv;                           // sum over warps >= lane
        if (lane == 0) s_wsuf[32] = 0;
    }
    __syncthreads();
    int suffix_incl = v + s_wsuf[wrp + 1];           // sum over threads >= t

    int run = suffix_incl - own;
    int lmax = 0;
#pragma unroll
    for (int k = 3; k >= 0; k--) {
        s_base[b0 + k] = run;
        s_cur[b0 + k]  = run;
        if (run < KSEL && h[k] > 0) {
            int e = run + h[k];
            if (e > lmax) lmax = e;
        }
        run += h[k];
    }
    if (lmax) atomicMax(&s_max, lmax);
    __syncthreads();

    const int candcnt = s_max;
    const int ovf = (candcnt > CAND_CAP);            // adversarial-data fallback
    unsigned long long* keys = ovf ? &g_cand[b][0] : s_keys;

    // ---- scatter precomputed keys, bucket-grouped ----
#pragma unroll 4
    for (int k = 0; k < 32; k++) {
        unsigned long long key = kf[k * 1024 + t];   // coalesced 8B loads
        int bk = bucket_of((unsigned)(key >> 32));
        if (s_base[bk] < KSEL) {
            int pos = atomicAdd(&s_cur[bk], 1);      // pos in [base, base+cnt)
            keys[pos] = key;
        }
    }
    __syncthreads();

    // ---- rank within segment + gather boxes ----
    for (int slot = t; slot < candcnt; slot += 1024) {
        unsigned long long key = keys[slot];
        unsigned u = (unsigned)(key >> 32);
        int bk = bucket_of(u);
        int segbase = s_base[bk];
        if (segbase >= KSEL) continue;               // safety
        int above = (bk > 0) ? s_base[bk - 1] : NPTS;
        int segcnt = above - segbase;
        int rank = segbase;
        if (segcnt > 1) {
            int gt = 0;
#pragma unroll 4
            for (int m = 0; m < segcnt; m++) gt += (keys[segbase + m] > key);
            rank += gt;                              // keys distinct -> unique ranks
        }
        if (rank >= KSEL) continue;

        int idx = (int)(0xFFFFFFFFu - (unsigned)key);
        const float* bx = bx0 + (size_t)idx * 7;
        float v0 = bx[0], v1 = bx[1], v2 = bx[2], v3 = bx[3],
              v4 = bx[4], v5 = bx[5], v6 = bx[6];
        float* ro = &g_rois[b][rank][0];
        ro[0] = v0; ro[1] = v1; ro[2] = v2; ro[3] = v3;
        ro[4] = v4; ro[5] = v5; ro[6] = v6;

        const float* cp = cb + (size_t)idx * NCLS;
        float c0 = cp[0], c1 = cp[1], c2 = cp[2];
        float s = c0; int lab = 0;
        if (c1 > s) { s = c1; lab = 1; }
        if (c2 > s) { s = c2; lab = 2; }
        g_scores[b][rank] = s;
        g_labels[b][rank] = (unsigned char)lab;

        float hx = __fmul_rn(0.5f, v3), hy = __fmul_rn(0.5f, v4);
        float x1 = __fsub_rn(v0, hx), x2 = __fadd_rn(v0, hx);
        float y1 = __fsub_rn(v1, hy), y2 = __fadd_rn(v1, hy);
        g_box4[b][rank] = make_float4(x1, y1, x2, y2);
        g_area[b][rank] = __fmul_rn(v3, v4);
    }
}

// ================= K3: mask + rownz, LAST block runs the scan tail ===========
// 128 threads: t<64 compute the mask block; after fence+counter, the last
// arriving block of each batch runs the full R16 scan (gather/greedy/compact).
__global__ void __launch_bounds__(128)
k_mask0_scan(float* __restrict__ out) {
    int cb = blockIdx.x, rb = blockIdx.y, b = blockIdx.z;
    int t = threadIdx.x;
    extern __shared__ unsigned char dsm[];
    unsigned long long* cm = (unsigned long long*)dsm;   // tail: rows [slot*17+cw]

    __shared__ float4 sb[64];
    __shared__ float  sa[64];
    __shared__ int s_last;

    // ---- mask work (upper-tri blocks only; all blocks reach the counter) ----
    if (cb >= rb) {
        if (t < 64) {
            sb[t] = g_box4[b][cb * 64 + t];
            sa[t] = g_area[b][cb * 64 + t];
        }
        __syncthreads();
        if (t < 64) {
            int i = rb * 64 + t;
            float4 me = g_box4[b][i];
            float  a  = g_area[b][i];
            unsigned long long m = 0;
            int j0 = (cb == rb) ? (t + 1) : 0;       // only j > i suppressed
            for (int jj = j0; jj < 64; jj++) {       // broadcast, conflict-free
                if (iou_gt(me, a, sb[jj], sa[jj])) m |= (1ull << jj);
            }
            g_mask0[b][(size_t)i * NW1 + cb] = m;

            unsigned bal = __ballot_sync(0xFFFFFFFFu, m != 0ull);
            if ((t & 31) == 0 && bal) {
                unsigned long long bits = (unsigned long long)bal << (t & 32);
                atomicOr(&g_rownz[b][rb], bits);
            }
        }
    }

    // ---- completion counting (threadfence-reduction pattern) ----
    __threadfence();
    if (t == 0) {
        int prev = atomicAdd(&g_blkdone[b], 1);
        s_last = (prev == NW1 * NW1 - 1);
        if (s_last) g_blkdone[b] = 0;                // reset for next replay
    }
    __syncthreads();
    if (!s_last) return;
    __threadfence();                                 // acquire all blocks' writes

    // ================= scan tail (128 threads) =================
    __shared__ unsigned long long rnz[NW1];
    __shared__ unsigned long long acc_s[NWORDS];
    __shared__ unsigned long long remv[NWORDS];      // fallback only
    __shared__ unsigned long long diag[64];          // fallback only
    __shared__ int s_fb;

    if (t < NWORDS) acc_s[t] = 0ull;
    if (t < NW1) rnz[t] = g_rownz[b][t];
    __syncthreads();

    int nrows = 0;
#pragma unroll
    for (int k = 0; k < NW1; k++) nrows += __popcll(rnz[k]);
    const bool use_smem = (nrows <= NCAP);

    // ---- sparse gather: each nonzero row -> one 128B line into smem ----
    if (use_smem) {
        for (int r = t; r < NW1 * 64; r += 128) {
            int w = r >> 6, bit = r & 63;
            if ((rnz[w] >> bit) & 1ull) {
                int slot = 0;
                for (int k = 0; k < w; k++) slot += __popcll(rnz[k]);
                slot += __popcll(rnz[w] & below_mask(bit));
                const unsigned long long* src = &g_mask0[b][(size_t)r * NW1];
#pragma unroll
                for (int cw = 0; cw < NW1; cw++)
                    cm[slot * 17 + cw] = src[cw];
            }
        }
    }
    __syncthreads();

    // ---- thread-0 greedy: rem[] in registers ----
    if (t == 0) {
        unsigned long long rem[NW1];
#pragma unroll
        for (int k = 0; k < NW1; k++) rem[k] = 0ull;
        int base = 0;
#pragma unroll
        for (int w = 0; w < NW1; w++) {
            unsigned long long rnzw = rnz[w];
            unsigned long long remw = rem[w];
            unsigned long long work = rnzw & ~remw;
            while (work) {
                int bit = __ffsll((long long)work) - 1;
                const unsigned long long* row;
                if (use_smem) {
                    int slot = base + __popcll(rnzw & below_mask(bit));
                    row = &cm[slot * 17];
                } else {
                    row = &g_mask0[b][(size_t)(w * 64 + bit) * NW1];
                }
                remw |= row[w];
#pragma unroll
                for (int cw = 0; cw < NW1; cw++)
                    if (cw != w) rem[cw] |= row[cw];
                work &= ~remw;
                work &= ~(1ull << bit);
            }
            rem[w] = remw;
            acc_s[w] = ~remw;
            base += __popcll(rnzw);
        }
        int cnt = 0;
#pragma unroll
        for (int w = 0; w < NW1; w++) cnt += __popcll(~rem[w]);
        s_fb = (cnt < KPOST);
    }
    __syncthreads();

    // ---- fallback: full 4096 NMS, per-column ownership (never taken) ----
    if (s_fb) {
        if (t < NWORDS) remv[t] = 0ull;
        __syncthreads();
        for (int w = 0; w < NWORDS; w++) {
            if (t < 64) {
                int i = w * 64 + t;
                float4 A = g_box4[b][i]; float aA = g_area[b][i];
                unsigned long long d = 0ull;
#pragma unroll 1
                for (int j = t + 1; j < 64; j++) {
                    int j2 = w * 64 + j;
                    if (iou_gt(A, aA, g_box4[b][j2], g_area[b][j2]))
                        d |= (1ull << j);
                }
                diag[t] = d;
            }
            __syncthreads();
            if (t == 0) {
                unsigned long long rem = remv[w], acc = 0ull;
#pragma unroll 1
                for (int bit = 0; bit < 64; bit++) {
                    if (!((rem >> bit) & 1ull)) { acc |= (1ull << bit); rem |= diag[bit]; }
                }
                acc_s[w] = acc;
            }
            __syncthreads();
            if (t < 64 && t > w) {                   // thread t owns column-word t
                unsigned long long aa = acc_s[w];
                unsigned long long p = 0ull;
                while (aa) {
                    int rbit = __ffsll((long long)aa) - 1;
                    aa &= aa - 1;
                    int i = w * 64 + rbit;
                    float4 A = g_box4[b][i]; float aA = g_area[b][i];
#pragma unroll 1
                    for (int j = 0; j < 64; j++) {
                        int j2 = t * 64 + j;
                        if (iou_gt(A, aA, g_box4[b][j2], g_area[b][j2]))
                            p |= (1ull << j);
                    }
                }
                remv[t] |= p;                        // own column: no atomics
            }
            __syncthreads();
        }
    }

    // ---- parallel compact: one thread per box computes its rank ----
    for (int r = t; r < KSEL; r += 128) {
        int w = r >> 6, bit = r & 63;
        unsigned long long acc = acc_s[w];
        if ((acc >> bit) & 1ull) {
            int rank = 0;
            for (int k = 0; k < w; k++) rank += __popcll(acc_s[k]);
            rank += __popcll(acc & below_mask(bit));
            if (rank < KPOST) {
                const float* ro = &g_rois[b][r][0];
                int obase = (b * KPOST + rank) * 7;
#pragma unroll
                for (int c = 0; c < 7; c++) out[obase + c] = ro[c];
                out[SC_OFF + b * KPOST + rank] = g_scores[b][r];
                out[LB_OFF + b * KPOST + rank] = (float)(g_labels[b][r] + 1);
            }
        }
    }
}

// ---------------- launch (3 kernels) ----------------
extern "C" void kernel_launch(void* const* d_in, const int* in_sizes, int n_in,
                              void* d_out, int out_size) {
    const float* boxes = (const float*)d_in[0];
    const float* cls   = (const float*)d_in[1];
    if (n_in >= 2 && in_sizes[0] == BATCH * NPTS * NCLS) {
        boxes = (const float*)d_in[1];
        cls   = (const float*)d_in[0];
    }
    float* out = (float*)d_out;

    const int DSM_SEL  = 16384 + 16384 + CAND_CAP * 8;   // 81920 B
    const int DSM_MS   = NCAP * 17 * 8;                  // 43520 B (tail rows)

    cudaFuncSetAttribute(k_select,
                         cudaFuncAttributeMaxDynamicSharedMemorySize, DSM_SEL);
    cudaFuncSetAttribute(k_mask0_scan,
                         cudaFuncAttributeMaxDynamicSharedMemorySize, DSM_MS);

    k_keys_hist<<<BATCH * NPTS / 256, 256>>>(cls, out);
    k_select<<<BATCH, 1024, DSM_SEL>>>(boxes, cls);
    k_mask0_scan<<<dim3(NW1, NW1, BATCH), 128, DSM_MS>>>(out);
}